// round 13
// baseline (speedup 1.0000x reference)
#include <cuda_runtime.h>

// ChamferDistance: B=8, N=M=8192, D=3.
// out = mean_over_y(min_over_x d2) + mean_over_x(min_over_y d2), d2 = squared L2.
//
// DESIGN FROZEN (R6, no hardware yet): brute-force pair sweep at the fma-pipe
// roofline. Per pair: 1.5 FFMA2 + 1.0 FMNMX + 0.125 LDS.128 — the no-packed-min
// floor. d2(x,y) = xn + (yn - 2 x.y); t = yn - 2x.y via a 3-FMA f32x2 chain
// (2 y-points/inst), xn added once per x at the end. SoA smem read as
// ulonglong2 so each LDS.128 yields two packed f32x2 operands directly.
// Predicted: ~2.8-3.0 ms, fma-pipe >= 90%, dram < 5%.

#define NPTS    8192
#define BATCH   8
#define THREADS 256
#define XPT     8                    // x points per thread
#define XTILE   (THREADS * XPT)      // 2048 x points per block
#define XTILES  (NPTS / XTILE)       // 4
#define YCHUNKS 32
#define YCHUNK  (NPTS / YCHUNKS)     // 256 y points per block (one smem stage)

typedef unsigned long long u64;

// Scratch: per-point running min, order-preserving uint encoding.
// [0][b][i] = min over y for x_i ; [1][b][i] = min over x for y_i
__device__ unsigned g_min[2 * BATCH * NPTS];

__device__ __forceinline__ u64 fma2(u64 a, u64 b, u64 c) {
    u64 d;
    asm("fma.rn.f32x2 %0, %1, %2, %3;" : "=l"(d) : "l"(a), "l"(b), "l"(c));
    return d;
}
__device__ __forceinline__ u64 pack2(float lo, float hi) {
    u64 d;
    asm("mov.b64 %0, {%1, %2};" : "=l"(d) : "f"(lo), "f"(hi));
    return d;
}
__device__ __forceinline__ void unpack2(float& lo, float& hi, u64 v) {
    asm("mov.b64 {%0, %1}, %2;" : "=f"(lo), "=f"(hi) : "l"(v));
}

// Order-preserving float <-> uint encoding (handles small negatives).
__device__ __forceinline__ unsigned encf(float f) {
    unsigned u = __float_as_uint(f);
    return (u & 0x80000000u) ? ~u : (u | 0x80000000u);
}
__device__ __forceinline__ float decf(unsigned e) {
    return (e & 0x80000000u) ? __uint_as_float(e ^ 0x80000000u)
                             : __uint_as_float(~e);
}

__global__ void init_kernel() {
    int i = blockIdx.x * blockDim.x + threadIdx.x;
    if (i < 2 * BATCH * NPTS) g_min[i] = 0xFFFFFFFFu;   // encoded +max
}

__global__ __launch_bounds__(THREADS)
void chamfer_kernel(const float* __restrict__ x, const float* __restrict__ y) {
    __shared__ __align__(16) float sy0[YCHUNK];
    __shared__ __align__(16) float sy1[YCHUNK];
    __shared__ __align__(16) float sy2[YCHUNK];
    __shared__ __align__(16) float syn[YCHUNK];

    const int tid    = threadIdx.x;
    const int xtile  = blockIdx.x;        // 0..XTILES-1
    const int ychunk = blockIdx.y;        // 0..YCHUNKS-1
    const int b      = blockIdx.z >> 1;   // batch
    const int dir    = blockIdx.z & 1;    // 0: queries=x, targets=y; 1: swapped

    const float* __restrict__ A  = dir ? y : x;   // query points
    const float* __restrict__ Bp = dir ? x : y;   // target points
    const float* Ab = A  + (size_t)b * NPTS * 3;
    const float* Bb = Bp + (size_t)b * NPTS * 3;

    const int xbase = xtile * XTILE + tid;

    // Issue x-point loads FIRST so their (first-wave) DRAM latency overlaps
    // the y staging stream below.
    float ax0[XPT], ax1[XPT], ax2[XPT];
#pragma unroll
    for (int p = 0; p < XPT; p++) {
        const int xi = xbase + p * THREADS;
        ax0[p] = Ab[xi * 3 + 0];
        ax1[p] = Ab[xi * 3 + 1];
        ax2[p] = Ab[xi * 3 + 2];
    }

    // Stage this block's y-chunk into SoA smem with precomputed norms.
    const int ybase = ychunk * YCHUNK;
    for (int j = tid; j < YCHUNK; j += THREADS) {
        const int yi = ybase + j;
        const float b0 = Bb[yi * 3 + 0];
        const float b1 = Bb[yi * 3 + 1];
        const float b2 = Bb[yi * 3 + 2];
        sy0[j] = b0; sy1[j] = b1; sy2[j] = b2;
        syn[j] = b0 * b0 + b1 * b1 + b2 * b2;
    }

    float xn[XPT];
    u64   m2x0[XPT], m2x1[XPT], m2x2[XPT];
    float mnl[XPT], mnh[XPT];

#pragma unroll
    for (int p = 0; p < XPT; p++) {
        xn[p]   = ax0[p] * ax0[p] + ax1[p] * ax1[p] + ax2[p] * ax2[p];
        m2x0[p] = pack2(-2.0f * ax0[p], -2.0f * ax0[p]);
        m2x1[p] = pack2(-2.0f * ax1[p], -2.0f * ax1[p]);
        m2x2[p] = pack2(-2.0f * ax2[p], -2.0f * ax2[p]);
        mnl[p]  = 3.4e38f;
        mnh[p]  = 3.4e38f;
    }

    __syncthreads();

    // Main sweep: 4 y-points per iteration. Each LDS.128 (ulonglong2) yields
    // two ready-to-use f32x2 operands: {y[j],y[j+1]} and {y[j+2],y[j+3]}.
#pragma unroll 2
    for (int j = 0; j < YCHUNK; j += 4) {
        const ulonglong2 Y0 = *(const ulonglong2*)&sy0[j];
        const ulonglong2 Y1 = *(const ulonglong2*)&sy1[j];
        const ulonglong2 Y2 = *(const ulonglong2*)&sy2[j];
        const ulonglong2 YN = *(const ulonglong2*)&syn[j];
#pragma unroll
        for (int p = 0; p < XPT; p++) {
            u64 ta = fma2(m2x0[p], Y0.x, YN.x);    // yn - 2x0*y0
            u64 tb = fma2(m2x0[p], Y0.y, YN.y);
            ta = fma2(m2x1[p], Y1.x, ta);
            tb = fma2(m2x1[p], Y1.y, tb);
            ta = fma2(m2x2[p], Y2.x, ta);
            tb = fma2(m2x2[p], Y2.y, tb);
            float la, ha, lb, hb;
            unpack2(la, ha, ta);
            unpack2(lb, hb, tb);
            mnl[p] = fminf(mnl[p], fminf(la, lb));
            mnh[p] = fminf(mnh[p], fminf(ha, hb));
        }
    }

    unsigned* gm = &g_min[dir * (BATCH * NPTS) + b * NPTS];
#pragma unroll
    for (int p = 0; p < XPT; p++) {
        const int xi = xbase + p * THREADS;
        const float d = xn[p] + fminf(mnl[p], mnh[p]);
        atomicMin(&gm[xi], encf(d));
    }
}

__global__ void reduce_kernel(float* __restrict__ out) {
    __shared__ double sred[32];
    const int tid = threadIdx.x;
    double s = 0.0;
    for (int i = tid; i < 2 * BATCH * NPTS; i += 1024)
        s += (double)decf(g_min[i]);
#pragma unroll
    for (int o = 16; o; o >>= 1) s += __shfl_down_sync(0xffffffffu, s, o);
    if ((tid & 31) == 0) sred[tid >> 5] = s;
    __syncthreads();
    if (tid < 32) {
        double v = sred[tid];
#pragma unroll
        for (int o = 16; o; o >>= 1) v += __shfl_down_sync(0xffffffffu, v, o);
        if (tid == 0)
            out[0] = (float)(v / (double)(BATCH * NPTS));  // N==M: one divisor
    }
}

extern "C" void kernel_launch(void* const* d_in, const int* in_sizes, int n_in,
                              void* d_out, int out_size) {
    const float* x = (const float*)d_in[0];
    const float* y = (const float*)d_in[1];
    (void)in_sizes; (void)n_in; (void)out_size;

    init_kernel<<<(2 * BATCH * NPTS + 255) / 256, 256>>>();

    dim3 grid(XTILES, YCHUNKS, BATCH * 2);   // 4 x 32 x 16 = 2048 blocks
    chamfer_kernel<<<grid, THREADS>>>(x, y);

    reduce_kernel<<<1, 1024>>>((float*)d_out);
}